// round 8
// baseline (speedup 1.0000x reference)
#include <cuda_runtime.h>
#include <cuda_bf16.h>
#include <math.h>
#include <stdint.h>

// Problem constants
#define BB 32
#define SS 1024
#define DIN 128
#define HH 256
#define G4H 1024          // 4*H
#define MROWS 32768       // B*S

// Recurrence decomposition: 2 dirs x 8 batch-groups x 8 hidden-split CTAs
#define CL 8              // cluster size (hidden split)
#define WSTRIDE 260       // W_sh row stride (floats): banks (4r+k)%32, 16B-aligned
#define HSTRIDE 260       // h_sh row stride

// ---------------- scratch (static device allocations; no cudaMalloc) -------
__device__ float g_xp_f[SS * BB * G4H];   // 134 MB  [t][b][4H]
__device__ float g_xp_b[SS * BB * G4H];   // 134 MB
__device__ float g_h0[BB * SS * 512];     // 67 MB   [b][t][512]
__device__ float g_h1[BB * SS * 512];     // 67 MB
__device__ float g_ctx[BB * SS * 512];    // 67 MB

__device__ __forceinline__ uint32_t smem_u32(const void* p) {
    uint32_t a;
    asm("{ .reg .u64 t; cvta.to.shared.u64 t, %1; cvt.u32.u64 %0, t; }"
        : "=r"(a) : "l"(p));
    return a;
}

// ---------------- tf32 tensor-core GEMM ------------------------------------
// out[r][n] = sum_k A[r][k] * W[n][k] + bias[n]
// mode 0: tile row R -> A row at (R&31)*sB + (R>>5)*sT  (xp layout)
// mode 1: A row at R*K
#define BK 32
#define KSTRIDE 136

__device__ __forceinline__ void mma_tf32(float* c, const uint32_t* a, const uint32_t* b) {
    asm volatile(
        "mma.sync.aligned.m16n8k8.row.col.f32.tf32.tf32.f32 "
        "{%0,%1,%2,%3}, {%4,%5,%6,%7}, {%8,%9}, {%0,%1,%2,%3};"
        : "+f"(c[0]), "+f"(c[1]), "+f"(c[2]), "+f"(c[3])
        : "r"(a[0]), "r"(a[1]), "r"(a[2]), "r"(a[3]), "r"(b[0]), "r"(b[1]));
}

__global__ void __launch_bounds__(256, 2) gemm_kernel(
    const float* __restrict__ Aext, int asel,
    const float* __restrict__ W, const float* __restrict__ bias,
    float* __restrict__ outext, int osel,
    int N, int K, long sB, long sT, int mode)
{
    const float* A = (asel == 0) ? Aext : (asel == 1 ? g_h0 : g_ctx);
    float* out = (osel == 2) ? outext : (osel == 0 ? g_xp_f : g_xp_b);

    __shared__ float As[BK][KSTRIDE];
    __shared__ float Bs[BK][KSTRIDE];

    int tid  = threadIdx.x;
    int row0 = blockIdx.x * 128;
    int col0 = blockIdx.y * 128;

    int lr = tid & 127;
    int lh = (tid >> 7) * 16;

    long aoff;
    if (mode == 0) { int R = row0 + lr; aoff = (long)(R & 31) * sB + (long)(R >> 5) * sT; }
    else           { aoff = (long)(row0 + lr) * K; }
    const float* Ap = A + aoff + lh;
    const float* Wp = W + (long)(col0 + lr) * K + lh;

    int lane = tid & 31, warp = tid >> 5;
    int wm = warp >> 1, wn = warp & 1;
    int gid = lane >> 2, tid4 = lane & 3;

    float acc[2][8][4];
#pragma unroll
    for (int mi = 0; mi < 2; mi++)
#pragma unroll
        for (int ni = 0; ni < 8; ni++)
#pragma unroll
            for (int q = 0; q < 4; q++) acc[mi][ni][q] = 0.f;

    for (int k0 = 0; k0 < K; k0 += BK) {
#pragma unroll
        for (int c = 0; c < 4; c++) {
            float4 av = *(const float4*)(Ap + k0 + c * 4);
            float4 wv = *(const float4*)(Wp + k0 + c * 4);
            int kk = lh + c * 4;
            As[kk + 0][lr] = av.x; As[kk + 1][lr] = av.y;
            As[kk + 2][lr] = av.z; As[kk + 3][lr] = av.w;
            Bs[kk + 0][lr] = wv.x; Bs[kk + 1][lr] = wv.y;
            Bs[kk + 2][lr] = wv.z; Bs[kk + 3][lr] = wv.w;
        }
        __syncthreads();

#pragma unroll
        for (int kk = 0; kk < BK; kk += 8) {
            uint32_t af[2][4];
#pragma unroll
            for (int mi = 0; mi < 2; mi++) {
                int r0 = wm * 32 + mi * 16 + gid;
                af[mi][0] = __float_as_uint(As[kk + tid4][r0]);
                af[mi][1] = __float_as_uint(As[kk + tid4][r0 + 8]);
                af[mi][2] = __float_as_uint(As[kk + tid4 + 4][r0]);
                af[mi][3] = __float_as_uint(As[kk + tid4 + 4][r0 + 8]);
            }
            uint32_t bf[8][2];
#pragma unroll
            for (int ni = 0; ni < 8; ni++) {
                int n0 = wn * 64 + ni * 8 + gid;
                bf[ni][0] = __float_as_uint(Bs[kk + tid4][n0]);
                bf[ni][1] = __float_as_uint(Bs[kk + tid4 + 4][n0]);
            }
#pragma unroll
            for (int mi = 0; mi < 2; mi++)
#pragma unroll
                for (int ni = 0; ni < 8; ni++)
                    mma_tf32(acc[mi][ni], af[mi], bf[ni]);
        }
        __syncthreads();
    }

#pragma unroll
    for (int mi = 0; mi < 2; mi++) {
        int r = row0 + wm * 32 + mi * 16 + gid;
#pragma unroll
        for (int ni = 0; ni < 8; ni++) {
            int cc = col0 + wn * 64 + ni * 8 + tid4 * 2;
            float b0 = bias[cc], b1 = bias[cc + 1];
            float2 v0 = make_float2(acc[mi][ni][0] + b0, acc[mi][ni][1] + b1);
            float2 v1 = make_float2(acc[mi][ni][2] + b0, acc[mi][ni][3] + b1);
            *(float2*)(out + (long)r * N + cc)       = v0;
            *(float2*)(out + (long)(r + 8) * N + cc) = v1;
        }
    }
}

// ---------------- recurrence: CGA-cluster version ---------------------------
// grid = 128 CTAs = 16 clusters of 8. cluster cidx: dir = cidx>>3, bgroup = cidx&7.
// Each CTA: 32 hidden units (all 4 gates = 128 gate rows) x 4 batches.
// h exchange via DSMEM pushes + barrier.cluster per step. No global sync.
__global__ void __launch_bounds__(256, 1) __cluster_dims__(CL, 1, 1)
rec_kernel(const float* __restrict__ w_hh_f, const float* __restrict__ w_hh_b,
           int layer)
{
    extern __shared__ float sm[];
    float* W_sh = sm;                          // [128][WSTRIDE]
    float* h_sh = sm + 128 * WSTRIDE;          // [2][4][HSTRIDE]
    float* g_sh = h_sh + 2 * 4 * HSTRIDE;      // [128][4]

    int tid = threadIdx.x;
    unsigned crank;
    asm("mov.u32 %0, %%cluster_ctarank;" : "=r"(crank));
    int cidx = blockIdx.x / CL;
    int dir  = cidx >> 3;
    int bg   = cidx & 7;

    const float* Whh = dir ? w_hh_b : w_hh_f;
    const float* xp  = dir ? g_xp_b : g_xp_f;
    float* hout = layer ? g_h1 : g_h0;

    // W slice: local row r (= q*32 + jl) -> global gate row q*HH + crank*32 + jl
    for (int i = tid; i < 128 * 256; i += 256) {
        int r = i >> 8, k = i & 255;
        int grow = (r >> 5) * HH + (int)crank * 32 + (r & 31);
        W_sh[r * WSTRIDE + k] = Whh[(long)grow * HH + k];
    }
    for (int i = tid; i < 2 * 4 * HSTRIDE; i += 256) h_sh[i] = 0.f;
    __syncthreads();
    asm volatile("barrier.cluster.arrive.aligned;" ::: "memory");
    asm volatile("barrier.cluster.wait.aligned;"   ::: "memory");

    // GEMV mapping: warp w, lane l: rsub = l>>2, b = l&3; rows r0 = w*16+rsub, r1 = r0+8
    int lane = tid & 31, w = tid >> 5;
    int rsub = lane >> 2, b = lane & 3;
    int r0 = w * 16 + rsub, r1 = r0 + 8;
    long grow0 = (long)(r0 >> 5) * HH + crank * 32 + (r0 & 31);
    long grow1 = (long)(r1 >> 5) * HH + crank * 32 + (r1 & 31);
    int b_global = bg * 4 + b;

    // nonlin mapping (tid < 128): hidden jl = tid>>2, batch nb = tid&3
    int njl = tid >> 2, nb = tid & 3;
    float c = 0.f;

    uint32_t h_u32 = smem_u32(h_sh);

    for (int t = 0; t < SS; t++) {
        int tt = dir ? (SS - 1 - t) : t;
        int rbuf = t & 1, wbuf = rbuf ^ 1;

        // x preactivations (global loads; overlap with smem GEMV below)
        long xb = (long)tt * (BB * G4H) + (long)b_global * G4H;
        float xv0 = xp[xb + grow0];
        float xv1 = xp[xb + grow1];

        const float* w0 = W_sh + r0 * WSTRIDE;
        const float* w1 = W_sh + r1 * WSTRIDE;
        const float* hv = h_sh + (rbuf * 4 + b) * HSTRIDE;

        float s0a = 0.f, s0b = 0.f, s1a = 0.f, s1b = 0.f;
#pragma unroll
        for (int k = 0; k < 256; k += 8) {
            float4 wa0 = *(const float4*)(w0 + k);
            float4 wa1 = *(const float4*)(w0 + k + 4);
            float4 wb0 = *(const float4*)(w1 + k);
            float4 wb1 = *(const float4*)(w1 + k + 4);
            float4 ha  = *(const float4*)(hv + k);
            float4 hbv = *(const float4*)(hv + k + 4);
            s0a = fmaf(wa0.x, ha.x,  s0a); s1a = fmaf(wb0.x, ha.x,  s1a);
            s0a = fmaf(wa0.y, ha.y,  s0a); s1a = fmaf(wb0.y, ha.y,  s1a);
            s0a = fmaf(wa0.z, ha.z,  s0a); s1a = fmaf(wb0.z, ha.z,  s1a);
            s0a = fmaf(wa0.w, ha.w,  s0a); s1a = fmaf(wb0.w, ha.w,  s1a);
            s0b = fmaf(wa1.x, hbv.x, s0b); s1b = fmaf(wb1.x, hbv.x, s1b);
            s0b = fmaf(wa1.y, hbv.y, s0b); s1b = fmaf(wb1.y, hbv.y, s1b);
            s0b = fmaf(wa1.z, hbv.z, s0b); s1b = fmaf(wb1.z, hbv.z, s1b);
            s0b = fmaf(wa1.w, hbv.w, s0b); s1b = fmaf(wb1.w, hbv.w, s1b);
        }
        g_sh[r0 * 4 + b] = s0a + s0b + xv0;
        g_sh[r1 * 4 + b] = s1a + s1b + xv1;
        __syncthreads();

        if (tid < 128) {
            float gi = g_sh[(0 * 32 + njl) * 4 + nb];
            float gf = g_sh[(1 * 32 + njl) * 4 + nb];
            float gg = g_sh[(2 * 32 + njl) * 4 + nb];
            float go = g_sh[(3 * 32 + njl) * 4 + nb];
            float si = 1.f / (1.f + expf(-gi));
            float sf = 1.f / (1.f + expf(-gf));
            float so = 1.f / (1.f + expf(-go));
            float tg = tanhf(gg);
            c = sf * c + si * tg;
            float hval = so * tanhf(c);

            // layer output [b][t][512]
            hout[((long)(bg * 4 + nb) * SS + tt) * 512 + dir * HH + crank * 32 + njl] = hval;

            // push h to all 8 cluster CTAs' write buffer (incl. self)
            if (t < SS - 1) {
                uint32_t off = h_u32 +
                    (uint32_t)(((wbuf * 4 + nb) * HSTRIDE + (int)crank * 32 + njl) * 4);
#pragma unroll
                for (int pr = 0; pr < CL; pr++) {
                    uint32_t rem;
                    asm("mapa.shared::cluster.u32 %0, %1, %2;"
                        : "=r"(rem) : "r"(off), "r"(pr));
                    asm volatile("st.shared::cluster.f32 [%0], %1;"
                                 :: "r"(rem), "f"(hval) : "memory");
                }
            }
        }

        if (t < SS - 1) {
            // cluster barrier: orders DSMEM pushes before next step's reads,
            // and doubles as the CTA-wide barrier for g_sh/h_sh reuse.
            asm volatile("barrier.cluster.arrive.aligned;" ::: "memory");
            asm volatile("barrier.cluster.wait.aligned;"   ::: "memory");
        }
    }
}

// ---------------- attention: causal softmax-weighted running average -------
__global__ void __launch_bounds__(512) attn_kernel(
    const float* __restrict__ attn_w, const float* __restrict__ attn_b)
{
    __shared__ float aw[512];
    __shared__ float e_sh[SS];
    __shared__ float red[16];

    int b = blockIdx.x, tid = threadIdx.x;
    int lane = tid & 31, warp = tid >> 5;
    const float* hb = g_h1 + (long)b * SS * 512;

    aw[tid] = attn_w[tid];
    float sb = attn_b[0];
    __syncthreads();

    for (int t = warp; t < SS; t += 16) {
        const float* hp = hb + (long)t * 512;
        float s = 0.f;
#pragma unroll
        for (int i = lane; i < 512; i += 32) s = fmaf(hp[i], aw[i], s);
#pragma unroll
        for (int o = 16; o; o >>= 1) s += __shfl_xor_sync(0xffffffffu, s, o);
        if (lane == 0) e_sh[t] = s + sb;
    }
    __syncthreads();

    float m = -3.4e38f;
    for (int t = tid; t < SS; t += 512) m = fmaxf(m, e_sh[t]);
#pragma unroll
    for (int o = 16; o; o >>= 1) m = fmaxf(m, __shfl_xor_sync(0xffffffffu, m, o));
    if (lane == 0) red[warp] = m;
    __syncthreads();
    m = red[0];
#pragma unroll
    for (int i = 1; i < 16; i++) m = fmaxf(m, red[i]);

    for (int t = tid; t < SS; t += 512) e_sh[t] = expf(e_sh[t] - m);
    __syncthreads();

    int d = tid;
    float num = 0.f, den = 0.f;
    const float* hd = hb + d;
    float* cd = g_ctx + (long)b * SS * 512 + d;
    for (int t = 0; t < SS; t++) {
        float ev = e_sh[t];
        den += ev;
        num = fmaf(ev, hd[(long)t * 512], num);
        cd[(long)t * 512] = num / den;
    }
}

// ---------------- launch ----------------------------------------------------
extern "C" void kernel_launch(void* const* d_in, const int* in_sizes, int n_in,
                              void* d_out, int out_size)
{
    const float* x       = (const float*)d_in[0];
    const float* wih0f   = (const float*)d_in[1];
    const float* whh0f   = (const float*)d_in[2];
    const float* b0f     = (const float*)d_in[3];
    const float* wih0b   = (const float*)d_in[4];
    const float* whh0b   = (const float*)d_in[5];
    const float* b0b     = (const float*)d_in[6];
    const float* wih1f   = (const float*)d_in[7];
    const float* whh1f   = (const float*)d_in[8];
    const float* b1f     = (const float*)d_in[9];
    const float* wih1b   = (const float*)d_in[10];
    const float* whh1b   = (const float*)d_in[11];
    const float* b1b     = (const float*)d_in[12];
    const float* attn_w  = (const float*)d_in[13];
    const float* attn_b  = (const float*)d_in[14];
    const float* head_w  = (const float*)d_in[15];
    const float* head_b  = (const float*)d_in[16];
    float* out = (float*)d_out;

    const int REC_SMEM = (128 * WSTRIDE + 2 * 4 * HSTRIDE + 128 * 4) * sizeof(float); // 143488
    cudaFuncSetAttribute(rec_kernel, cudaFuncAttributeMaxDynamicSharedMemorySize, REC_SMEM);

    // ---- layer 0 ----
    gemm_kernel<<<dim3(MROWS / 128, G4H / 128), 256>>>(x, 0, wih0f, b0f, nullptr, 0,
                                                       G4H, DIN, (long)SS * DIN, DIN, 0);
    gemm_kernel<<<dim3(MROWS / 128, G4H / 128), 256>>>(x, 0, wih0b, b0b, nullptr, 1,
                                                       G4H, DIN, (long)SS * DIN, DIN, 0);
    rec_kernel<<<128, 256, REC_SMEM>>>(whh0f, whh0b, 0);

    // ---- layer 1 ----
    gemm_kernel<<<dim3(MROWS / 128, G4H / 128), 256>>>(nullptr, 1, wih1f, b1f, nullptr, 0,
                                                       G4H, 512, (long)SS * 512, 512, 0);
    gemm_kernel<<<dim3(MROWS / 128, G4H / 128), 256>>>(nullptr, 1, wih1b, b1b, nullptr, 1,
                                                       G4H, 512, (long)SS * 512, 512, 0);
    rec_kernel<<<128, 256, REC_SMEM>>>(whh1f, whh1b, 1);

    // ---- attention + head ----
    attn_kernel<<<BB, 512>>>(attn_w, attn_b);
    gemm_kernel<<<dim3(MROWS / 128, 1), 256>>>(nullptr, 2, head_w, head_b, out, 2,
                                               DIN, 512, 0, 0, 1);
}